// round 12
// baseline (speedup 1.0000x reference)
#include <cuda_runtime.h>
#include <cuda_fp16.h>
#include <math.h>
#include <stdint.h>

// Problem dims (fixed by the reference)
#define BB 2
#define TT 2048
#define CC 1024
#define NH 16
#define HD 64
#define MROWS (BB*TT)   // 4096

// Scratch (allocation-free rule: __device__ globals)
__device__ __half g_qk[(size_t)MROWS * 2 * CC];   // Q,K packed [t][2048] half
__device__ __half g_vt[(size_t)CC * MROWS];       // V^T [h*64+d][b*TT+t] half
__device__ __half g_xh[(size_t)MROWS * CC];       // x as half [M][K]
__device__ __half g_waT[(size_t)(3*CC) * CC];     // w_attn^T [3C][C] half
__device__ __half g_wpT[(size_t)CC * CC];         // w_proj^T [C][C] half
__device__ __half g_yh[(size_t)MROWS * CC];       // attention out half [M][C]

// ---------------------------------------------------------------------------
// mma.sync m16n8k16 fp16 -> fp32 accum
__device__ __forceinline__ void mma_f16(float c[4], const uint32_t a[4], const uint32_t b[2]) {
    asm volatile(
        "mma.sync.aligned.m16n8k16.row.col.f32.f16.f16.f32 "
        "{%0,%1,%2,%3}, {%4,%5,%6,%7}, {%8,%9}, {%0,%1,%2,%3};"
        : "+f"(c[0]), "+f"(c[1]), "+f"(c[2]), "+f"(c[3])
        : "r"(a[0]), "r"(a[1]), "r"(a[2]), "r"(a[3]), "r"(b[0]), "r"(b[1]));
}

// ldmatrix x4: one instruction loads four 8x8 b16 matrices (A-frag or 2 B-frags)
__device__ __forceinline__ void ldm_x4(uint32_t r[4], uint32_t addr) {
    asm volatile("ldmatrix.sync.aligned.m8n8.x4.shared.b16 {%0,%1,%2,%3}, [%4];"
        : "=r"(r[0]), "=r"(r[1]), "=r"(r[2]), "=r"(r[3]) : "r"(addr));
}

__device__ __forceinline__ uint32_t smem_u32(const void* p) {
    uint32_t a;
    asm("{ .reg .u64 t; cvta.to.shared.u64 t, %1; cvt.u32.u64 %0, t; }" : "=r"(a) : "l"(p));
    return a;
}
__device__ __forceinline__ void cp_async16(uint32_t dst, const void* src) {
    asm volatile("cp.async.cg.shared.global [%0], [%1], 16;" :: "r"(dst), "l"(src) : "memory");
}
__device__ __forceinline__ void cp_commit() {
    asm volatile("cp.async.commit_group;" ::: "memory");
}
template <int N>
__device__ __forceinline__ void cp_wait() {
    asm volatile("cp.async.wait_group %0;" :: "n"(N) : "memory");
}

// ---------------------------------------------------------------------------
// prep kernels: x -> half; w -> half transposed [N][K]
// ---------------------------------------------------------------------------
__global__ void conv_half(const float* __restrict__ in, __half* __restrict__ out, int n4) {
    int i = blockIdx.x * blockDim.x + threadIdx.x;
    int stride = gridDim.x * blockDim.x;
    for (; i < n4; i += stride) {
        float4 v = ((const float4*)in)[i];
        ((__half2*)out)[2 * i + 0] = __floats2half2_rn(v.x, v.y);
        ((__half2*)out)[2 * i + 1] = __floats2half2_rn(v.z, v.w);
    }
}

// in: fp32 [K][N]; out: half [N][K]. block (32,8), grid (N/32, K/32)
__global__ void transpose_half(const float* __restrict__ in, __half* __restrict__ out,
                               int K, int N) {
    __shared__ float tile[32][33];
    const int n0 = blockIdx.x * 32, k0 = blockIdx.y * 32;
    #pragma unroll
    for (int r = threadIdx.y; r < 32; r += 8)
        tile[r][threadIdx.x] = in[(size_t)(k0 + r) * N + n0 + threadIdx.x];
    __syncthreads();
    #pragma unroll
    for (int r = threadIdx.y; r < 32; r += 8)
        out[(size_t)(n0 + r) * K + k0 + threadIdx.x] = __float2half_rn(tile[threadIdx.x][r]);
}

// ---------------------------------------------------------------------------
// fp16 mma.sync GEMM v5: C[M,N] = A[M,K] @ Bt[N,K]^T + bias[N]
// CTA 128x128, BK=64, 128 threads (4 warps, 2x2), warp tile 64x64.
// bytes/MMA = 128 (balance point of smem BW vs tensor rate).
// cp.async 3-stage pipeline; per stage A[128][72]h + B[128][72]h = 36864 B;
// 3 stages = 110592 B -> 2 CTAs/SM, 8 warps/SM.
// mode 0: fp32 out to Cf. mode 1 (QKV): cols<2048 -> half [t][2048] to qkh;
//         cols>=2048 -> transposed half to vt[d][t].
// ---------------------------------------------------------------------------
#define G_LD 72
#define G_STAGE_H 18432   // halves per stage
#define G_BHALF 9216      // B offset within stage (halves)
#define G_SMEM_B (3 * G_STAGE_H * 2)   // 110592

__global__ __launch_bounds__(128, 2)
void gemm_h(const __half* __restrict__ A, const __half* __restrict__ Bt,
            const float* __restrict__ bias, float* __restrict__ Cf,
            __half* __restrict__ qkh, __half* __restrict__ vt,
            int M, int N, int K, int mode)
{
    extern __shared__ __half smh[];
    const uint32_t sbase = smem_u32(smh);
    const int tid  = threadIdx.x;
    const int lane = tid & 31;
    const int wid  = tid >> 5;
    const int wm   = wid & 1;        // 0..1 (64-row block)
    const int wn   = wid >> 1;       // 0..1 (64-col block)
    const int brow = blockIdx.y, bcol = blockIdx.x;
    const int r4 = lane >> 2, c4 = lane & 3;

    const int NT = K / 64;

    auto issue_stage = [&](int kt, int s) {
        const uint32_t sb = sbase + (uint32_t)s * (G_STAGE_H * 2);
        #pragma unroll
        for (int i = 0; i < 8; i++) {
            int id = tid + i * 128;
            int row = id >> 3, ch = (id & 7) << 3;   // 64 halves = 8 chunks
            cp_async16(sb + (uint32_t)(row * G_LD + ch) * 2u,
                       A + (size_t)(brow * 128 + row) * K + kt * 64 + ch);
        }
        #pragma unroll
        for (int i = 0; i < 8; i++) {
            int id = tid + i * 128;
            int row = id >> 3, ch = (id & 7) << 3;
            cp_async16(sb + (uint32_t)(G_BHALF + row * G_LD + ch) * 2u,
                       Bt + (size_t)(bcol * 128 + row) * K + kt * 64 + ch);
        }
        cp_commit();
    };

    float acc[4][8][4];
    #pragma unroll
    for (int i = 0; i < 4; i++)
        #pragma unroll
        for (int j = 0; j < 8; j++)
            #pragma unroll
            for (int e = 0; e < 4; e++) acc[i][j][e] = 0.f;

    issue_stage(0, 0);
    issue_stage(1, 1);

    // ldmatrix lane-address components (halves)
    const int lA_row = lane & 15;           // row within 16-row strip
    const int lA_col = (lane >> 4) * 8;     // k-half select
    const int lB_row = (lane & 7) + (lane >> 4) * 8;   // row within 16-n block
    const int lB_col = ((lane >> 3) & 1) * 8;          // k-half select

    for (int kt = 0; kt < NT; kt++) {
        if (kt + 2 < NT) cp_wait<1>(); else cp_wait<0>();
        __syncthreads();
        if (kt + 2 < NT) issue_stage(kt + 2, (kt + 2) % 3);

        const uint32_t sAu = sbase + (uint32_t)((kt % 3) * G_STAGE_H) * 2u;
        const uint32_t sBu = sAu + G_BHALF * 2u;

        #pragma unroll
        for (int ks = 0; ks < 4; ks++) {
            uint32_t a[4][4], b[4][4];
            #pragma unroll
            for (int i = 0; i < 4; i++)
                ldm_x4(a[i], sAu + (uint32_t)((wm * 64 + i * 16 + lA_row) * G_LD
                                              + ks * 16 + lA_col) * 2u);
            #pragma unroll
            for (int jp = 0; jp < 4; jp++)
                ldm_x4(b[jp], sBu + (uint32_t)((wn * 64 + jp * 16 + lB_row) * G_LD
                                               + ks * 16 + lB_col) * 2u);
            #pragma unroll
            for (int i = 0; i < 4; i++)
                #pragma unroll
                for (int jp = 0; jp < 4; jp++) {
                    mma_f16(acc[i][2 * jp],     a[i], &b[jp][0]);
                    mma_f16(acc[i][2 * jp + 1], a[i], &b[jp][2]);
                }
        }
        __syncthreads();
    }

    // epilogue
    #pragma unroll
    for (int i = 0; i < 4; i++) {
        const int gm0 = brow * 128 + wm * 64 + i * 16 + r4;
        #pragma unroll
        for (int j = 0; j < 8; j++) {
            const int gn = bcol * 128 + wn * 64 + j * 8 + c4 * 2;
            const float b0 = bias[gn], b1 = bias[gn + 1];
            const float v00 = acc[i][j][0] + b0, v01 = acc[i][j][1] + b1;
            const float v10 = acc[i][j][2] + b0, v11 = acc[i][j][3] + b1;
            if (mode == 0) {
                *(float2*)(Cf + (size_t)gm0 * N + gn)       = make_float2(v00, v01);
                *(float2*)(Cf + (size_t)(gm0 + 8) * N + gn) = make_float2(v10, v11);
            } else if (gn < 2048) {
                *(__half2*)(qkh + (size_t)gm0 * 2048 + gn)       = __floats2half2_rn(v00, v01);
                *(__half2*)(qkh + (size_t)(gm0 + 8) * 2048 + gn) = __floats2half2_rn(v10, v11);
            } else {
                const int d = gn - 2048;
                vt[(size_t)d       * MROWS + gm0]     = __float2half_rn(v00);
                vt[(size_t)(d + 1) * MROWS + gm0]     = __float2half_rn(v01);
                vt[(size_t)d       * MROWS + gm0 + 8] = __float2half_rn(v10);
                vt[(size_t)(d + 1) * MROWS + gm0 + 8] = __float2half_rn(v11);
            }
        }
    }
}

// ---------------------------------------------------------------------------
// Flash attention fp16: mma.sync m16n8k16 + ldmatrix, fp32 online softmax.
// Grid (32, NH, BB), 128 threads (4 warps), warp m16 strip, BKV=64, D=64.
// SMEM (halves, LD=72): Q @0, P @4608, K dbl @9216/@13824, Vt dbl @18432/@23040.
// Total 27648 halves = 55296 B. K tile [key][d]; V tile [d_out][key] (g_vt).
// ---------------------------------------------------------------------------
#define FH_Q 0
#define FH_P 4608
#define FH_K 9216
#define FH_V 18432
#define FLASH_SMEM_B (27648 * 2)

__global__ __launch_bounds__(128, 3)
void flash_h(const __half* __restrict__ qkh, const __half* __restrict__ vt,
             __half* __restrict__ y)
{
    extern __shared__ __half smh[];
    const uint32_t sbase = smem_u32(smh);
    const int tid  = threadIdx.x;
    const int lane = tid & 31;
    const int w    = tid >> 5;
    const int r4   = lane >> 2;
    const int c4   = lane & 3;
    const int qt   = gridDim.x - 1 - blockIdx.x;   // big tiles first
    const int h    = blockIdx.y;
    const int b    = blockIdx.z;

    const __half* qg = qkh + (size_t)(b * TT + qt * 64) * 2048 + h * 64;
    const __half* kg = qkh + (size_t)(b * TT) * 2048 + 1024 + h * 64;
    const __half* vg = vt + (size_t)(h * 64) * MROWS + b * TT;

    auto issue_q = [&]() {
        #pragma unroll
        for (int i = 0; i < 4; i++) {
            int id = tid + i * 128;
            int row = id >> 3, ch = (id & 7) << 3;
            cp_async16(sbase + (uint32_t)(FH_Q + row * 72 + ch) * 2u,
                       qg + (size_t)row * 2048 + ch);
        }
    };
    auto issue_kv = [&](int j, int buf) {
        #pragma unroll
        for (int i = 0; i < 4; i++) {
            int id = tid + i * 128;
            int row = id >> 3, ch = (id & 7) << 3;
            cp_async16(sbase + (uint32_t)(FH_K + buf * 4608 + row * 72 + ch) * 2u,
                       kg + (size_t)(j * 64 + row) * 2048 + ch);
        }
        #pragma unroll
        for (int i = 0; i < 4; i++) {
            int id = tid + i * 128;
            int row = id >> 3, ch = (id & 7) << 3;   // row = d, ch = key chunk
            cp_async16(sbase + (uint32_t)(FH_V + buf * 4608 + row * 72 + ch) * 2u,
                       vg + (size_t)row * MROWS + j * 64 + ch);
        }
    };

    issue_q();
    issue_kv(0, 0);
    cp_commit();

    // ldmatrix lane-address components (halves)
    const int lA_row = lane & 15;
    const int lA_col = (lane >> 4) * 8;
    const int lB_row = (lane & 7) + (lane >> 4) * 8;
    const int lB_col = ((lane >> 3) & 1) * 8;

    uint32_t qa[4][4];
    float o[8][4];
    #pragma unroll
    for (int j2 = 0; j2 < 8; j2++)
        #pragma unroll
        for (int e = 0; e < 4; e++) o[j2][e] = 0.f;
    float m0 = -INFINITY, m1 = -INFINITY, l0 = 0.f, l1 = 0.f;

    for (int j = 0; j <= qt; j++) {
        cp_wait<0>();
        __syncthreads();
        if (j < qt) { issue_kv(j + 1, (j + 1) & 1); cp_commit(); }

        if (j == 0) {
            #pragma unroll
            for (int ks = 0; ks < 4; ks++)
                ldm_x4(qa[ks], sbase + (uint32_t)(FH_Q + (w * 16 + lA_row) * 72
                                                  + ks * 16 + lA_col) * 2u);
        }

        const uint32_t Ku = sbase + (uint32_t)(FH_K + (j & 1) * 4608) * 2u;
        const uint32_t Vu = sbase + (uint32_t)(FH_V + (j & 1) * 4608) * 2u;
        const uint32_t Pu = sbase + (uint32_t)FH_P * 2u;

        // S = Q @ K^T  (warp: m16 x n64)
        float c[8][4];
        #pragma unroll
        for (int j2 = 0; j2 < 8; j2++)
            #pragma unroll
            for (int e = 0; e < 4; e++) c[j2][e] = 0.f;

        #pragma unroll
        for (int ks = 0; ks < 4; ks++) {
            uint32_t bk[4][4];
            #pragma unroll
            for (int jp = 0; jp < 4; jp++)
                ldm_x4(bk[jp], Ku + (uint32_t)((jp * 16 + lB_row) * 72
                                               + ks * 16 + lB_col) * 2u);
            #pragma unroll
            for (int jp = 0; jp < 4; jp++) {
                mma_f16(c[2 * jp],     qa[ks], &bk[jp][0]);
                mma_f16(c[2 * jp + 1], qa[ks], &bk[jp][2]);
            }
        }

        // scale, then causal mask on diagonal tile
        #pragma unroll
        for (int j2 = 0; j2 < 8; j2++) {
            c[j2][0] *= 0.125f; c[j2][1] *= 0.125f;
            c[j2][2] *= 0.125f; c[j2][3] *= 0.125f;
        }
        if (j == qt) {
            const int row0 = w * 16 + r4, row1 = row0 + 8;
            #pragma unroll
            for (int j2 = 0; j2 < 8; j2++) {
                const int col = j2 * 8 + 2 * c4;
                if (col     > row0) c[j2][0] = -INFINITY;
                if (col + 1 > row0) c[j2][1] = -INFINITY;
                if (col     > row1) c[j2][2] = -INFINITY;
                if (col + 1 > row1) c[j2][3] = -INFINITY;
            }
        }

        // online softmax (rows r4 / r4+8, quad-reduced)
        float mx0 = -INFINITY, mx1 = -INFINITY;
        #pragma unroll
        for (int j2 = 0; j2 < 8; j2++) {
            mx0 = fmaxf(mx0, fmaxf(c[j2][0], c[j2][1]));
            mx1 = fmaxf(mx1, fmaxf(c[j2][2], c[j2][3]));
        }
        mx0 = fmaxf(mx0, __shfl_xor_sync(0xffffffffu, mx0, 1));
        mx0 = fmaxf(mx0, __shfl_xor_sync(0xffffffffu, mx0, 2));
        mx1 = fmaxf(mx1, __shfl_xor_sync(0xffffffffu, mx1, 1));
        mx1 = fmaxf(mx1, __shfl_xor_sync(0xffffffffu, mx1, 2));

        const float mn0 = fmaxf(m0, mx0), mn1 = fmaxf(m1, mx1);
        const float al0 = __expf(m0 - mn0), al1 = __expf(m1 - mn1);
        m0 = mn0; m1 = mn1;

        float ps0 = 0.f, ps1 = 0.f;
        #pragma unroll
        for (int j2 = 0; j2 < 8; j2++) {
            c[j2][0] = __expf(c[j2][0] - mn0);
            c[j2][1] = __expf(c[j2][1] - mn0);
            c[j2][2] = __expf(c[j2][2] - mn1);
            c[j2][3] = __expf(c[j2][3] - mn1);
            ps0 += c[j2][0] + c[j2][1];
            ps1 += c[j2][2] + c[j2][3];
        }
        ps0 += __shfl_xor_sync(0xffffffffu, ps0, 1);
        ps0 += __shfl_xor_sync(0xffffffffu, ps0, 2);
        ps1 += __shfl_xor_sync(0xffffffffu, ps1, 1);
        ps1 += __shfl_xor_sync(0xffffffffu, ps1, 2);
        l0 = l0 * al0 + ps0;
        l1 = l1 * al1 + ps1;

        #pragma unroll
        for (int j2 = 0; j2 < 8; j2++) {
            o[j2][0] *= al0; o[j2][1] *= al0;
            o[j2][2] *= al1; o[j2][3] *= al1;
        }

        // write P (half) to per-warp smem strip, reload as A-frags
        #pragma unroll
        for (int j2 = 0; j2 < 8; j2++) {
            *(__half2*)(smh + FH_P + (w * 16 + r4) * 72 + j2 * 8 + 2 * c4)
                = __floats2half2_rn(c[j2][0], c[j2][1]);
            *(__half2*)(smh + FH_P + (w * 16 + r4 + 8) * 72 + j2 * 8 + 2 * c4)
                = __floats2half2_rn(c[j2][2], c[j2][3]);
        }
        __syncwarp();

        // O += P @ V
        #pragma unroll
        for (int ks = 0; ks < 4; ks++) {
            uint32_t pa[4];
            ldm_x4(pa, Pu + (uint32_t)((w * 16 + lA_row) * 72 + ks * 16 + lA_col) * 2u);
            uint32_t bv[4][4];
            #pragma unroll
            for (int jp = 0; jp < 4; jp++)
                ldm_x4(bv[jp], Vu + (uint32_t)((jp * 16 + lB_row) * 72
                                               + ks * 16 + lB_col) * 2u);
            #pragma unroll
            for (int jp = 0; jp < 4; jp++) {
                mma_f16(o[2 * jp],     pa, &bv[jp][0]);
                mma_f16(o[2 * jp + 1], pa, &bv[jp][2]);
            }
        }
        __syncwarp();
    }

    // final store (half, feeds proj GEMM)
    const float il0 = 1.f / l0, il1 = 1.f / l1;
    const int gr0 = qt * 64 + w * 16 + r4;
    #pragma unroll
    for (int j2 = 0; j2 < 8; j2++) {
        const int col = h * HD + j2 * 8 + 2 * c4;
        *(__half2*)(y + (size_t)((size_t)b * TT + gr0) * CC + col)
            = __floats2half2_rn(o[j2][0] * il0, o[j2][1] * il0);
        *(__half2*)(y + (size_t)((size_t)b * TT + gr0 + 8) * CC + col)
            = __floats2half2_rn(o[j2][2] * il1, o[j2][3] * il1);
    }
}

// ---------------------------------------------------------------------------
extern "C" void kernel_launch(void* const* d_in, const int* in_sizes, int n_in,
                              void* d_out, int out_size)
{
    const float* x      = (const float*)d_in[0];
    const float* w_attn = (const float*)d_in[1];
    const float* b_attn = (const float*)d_in[2];
    const float* w_proj = (const float*)d_in[3];
    const float* b_proj = (const float*)d_in[4];
    float* out = (float*)d_out;

    __half *qk, *vt, *xh, *waT, *wpT, *yh;
    cudaGetSymbolAddress((void**)&qk,  g_qk);
    cudaGetSymbolAddress((void**)&vt,  g_vt);
    cudaGetSymbolAddress((void**)&xh,  g_xh);
    cudaGetSymbolAddress((void**)&waT, g_waT);
    cudaGetSymbolAddress((void**)&wpT, g_wpT);
    cudaGetSymbolAddress((void**)&yh,  g_yh);

    cudaFuncSetAttribute(gemm_h, cudaFuncAttributeMaxDynamicSharedMemorySize, G_SMEM_B);
    cudaFuncSetAttribute(flash_h, cudaFuncAttributeMaxDynamicSharedMemorySize, FLASH_SMEM_B);

    // prep: x -> half, weights -> half transposed
    conv_half<<<512, 256>>>(x, xh, MROWS * CC / 4);
    transpose_half<<<dim3(3 * CC / 32, CC / 32), dim3(32, 8)>>>(w_attn, waT, CC, 3 * CC);
    transpose_half<<<dim3(CC / 32, CC / 32), dim3(32, 8)>>>(w_proj, wpT, CC, CC);

    // 1) qkv = x @ w_attn + b_attn  (fp16 mma; Q,K -> g_qk; V -> g_vt transposed)
    gemm_h<<<dim3(3 * CC / 128, MROWS / 128), 128, G_SMEM_B>>>(
        xh, waT, b_attn, nullptr, qk, vt, MROWS, 3 * CC, CC, 1);

    // 2) flash attention (fp16 mma) -> g_yh
    flash_h<<<dim3(TT / 64, NH, BB), 128, FLASH_SMEM_B>>>(qk, vt, yh);

    // 3) out = y @ w_proj + b_proj  (fp16 mma; fp32 output)
    gemm_h<<<dim3(CC / 128, MROWS / 128), 128, G_SMEM_B>>>(
        yh, wpT, b_proj, out, nullptr, nullptr, MROWS, CC, CC, 0);
}

// round 13
// speedup vs baseline: 1.0099x; 1.0099x over previous
#include <cuda_runtime.h>
#include <cuda_fp16.h>
#include <math.h>
#include <stdint.h>

// Problem dims (fixed by the reference)
#define BB 2
#define TT 2048
#define CC 1024
#define NH 16
#define HD 64
#define MROWS (BB*TT)   // 4096

// Scratch (allocation-free rule: __device__ globals)
__device__ __half g_qk[(size_t)MROWS * 2 * CC];   // Q,K packed [t][2048] half
__device__ __half g_vt[(size_t)CC * MROWS];       // V^T [h*64+d][b*TT+t] half
__device__ __half g_xh[(size_t)MROWS * CC];       // x as half [M][K]
__device__ __half g_waT[(size_t)(3*CC) * CC];     // w_attn^T [3C][C] half
__device__ __half g_wpT[(size_t)CC * CC];         // w_proj^T [C][C] half
__device__ __half g_yh[(size_t)MROWS * CC];       // attention out half [M][C]

// ---------------------------------------------------------------------------
// mma.sync m16n8k16 fp16 -> fp32 accum
__device__ __forceinline__ void mma_f16(float c[4], const uint32_t a[4], const uint32_t b[2]) {
    asm volatile(
        "mma.sync.aligned.m16n8k16.row.col.f32.f16.f16.f32 "
        "{%0,%1,%2,%3}, {%4,%5,%6,%7}, {%8,%9}, {%0,%1,%2,%3};"
        : "+f"(c[0]), "+f"(c[1]), "+f"(c[2]), "+f"(c[3])
        : "r"(a[0]), "r"(a[1]), "r"(a[2]), "r"(a[3]), "r"(b[0]), "r"(b[1]));
}

// ldmatrix x4: one instruction loads four 8x8 b16 matrices (A-frag or 2 B-frags)
__device__ __forceinline__ void ldm_x4(uint32_t r[4], uint32_t addr) {
    asm volatile("ldmatrix.sync.aligned.m8n8.x4.shared.b16 {%0,%1,%2,%3}, [%4];"
        : "=r"(r[0]), "=r"(r[1]), "=r"(r[2]), "=r"(r[3]) : "r"(addr));
}

__device__ __forceinline__ uint32_t smem_u32(const void* p) {
    uint32_t a;
    asm("{ .reg .u64 t; cvta.to.shared.u64 t, %1; cvt.u32.u64 %0, t; }" : "=r"(a) : "l"(p));
    return a;
}
__device__ __forceinline__ void cp_async16(uint32_t dst, const void* src) {
    asm volatile("cp.async.cg.shared.global [%0], [%1], 16;" :: "r"(dst), "l"(src) : "memory");
}
__device__ __forceinline__ void cp_commit() {
    asm volatile("cp.async.commit_group;" ::: "memory");
}
template <int N>
__device__ __forceinline__ void cp_wait() {
    asm volatile("cp.async.wait_group %0;" :: "n"(N) : "memory");
}

// ---------------------------------------------------------------------------
// prep kernels: x -> half; w -> half transposed [N][K]
// ---------------------------------------------------------------------------
__global__ void conv_half(const float* __restrict__ in, __half* __restrict__ out, int n4) {
    int i = blockIdx.x * blockDim.x + threadIdx.x;
    int stride = gridDim.x * blockDim.x;
    for (; i < n4; i += stride) {
        float4 v = ((const float4*)in)[i];
        ((__half2*)out)[2 * i + 0] = __floats2half2_rn(v.x, v.y);
        ((__half2*)out)[2 * i + 1] = __floats2half2_rn(v.z, v.w);
    }
}

// in: fp32 [K][N]; out: half [N][K]. block (32,8), grid (N/32, K/32)
__global__ void transpose_half(const float* __restrict__ in, __half* __restrict__ out,
                               int K, int N) {
    __shared__ float tile[32][33];
    const int n0 = blockIdx.x * 32, k0 = blockIdx.y * 32;
    #pragma unroll
    for (int r = threadIdx.y; r < 32; r += 8)
        tile[r][threadIdx.x] = in[(size_t)(k0 + r) * N + n0 + threadIdx.x];
    __syncthreads();
    #pragma unroll
    for (int r = threadIdx.y; r < 32; r += 8)
        out[(size_t)(n0 + r) * K + k0 + threadIdx.x] = __float2half_rn(tile[threadIdx.x][r]);
}

// ---------------------------------------------------------------------------
// fp16 mma.sync GEMM v6: C[M,N] = A[M,K] @ Bt[N,K]^T + bias[N]
// CTA 128x128, BK=64, 128 threads (4 warps, 2x2), warp tile 64x64.
// Register double-buffered fragments: ldmatrix for ks+1 issued before MMAs
// of ks, hiding LDS latency behind 32 MMA issues.
// cp.async 3-stage pipeline; per stage A[128][72]h + B[128][72]h = 36864 B;
// 3 stages = 110592 B -> 2 CTAs/SM.
// mode 0: fp32 out to Cf. mode 1 (QKV): cols<2048 -> half [t][2048] to qkh;
//         cols>=2048 -> transposed half to vt[d][t].
// ---------------------------------------------------------------------------
#define G_LD 72
#define G_STAGE_H 18432   // halves per stage
#define G_BHALF 9216      // B offset within stage (halves)
#define G_SMEM_B (3 * G_STAGE_H * 2)   // 110592

__global__ __launch_bounds__(128, 2)
void gemm_h(const __half* __restrict__ A, const __half* __restrict__ Bt,
            const float* __restrict__ bias, float* __restrict__ Cf,
            __half* __restrict__ qkh, __half* __restrict__ vt,
            int M, int N, int K, int mode)
{
    extern __shared__ __half smh[];
    const uint32_t sbase = smem_u32(smh);
    const int tid  = threadIdx.x;
    const int lane = tid & 31;
    const int wid  = tid >> 5;
    const int wm   = wid & 1;        // 0..1 (64-row block)
    const int wn   = wid >> 1;       // 0..1 (64-col block)
    const int brow = blockIdx.y, bcol = blockIdx.x;
    const int r4 = lane >> 2, c4 = lane & 3;

    const int NT = K / 64;

    auto issue_stage = [&](int kt, int s) {
        const uint32_t sb = sbase + (uint32_t)s * (G_STAGE_H * 2);
        #pragma unroll
        for (int i = 0; i < 8; i++) {
            int id = tid + i * 128;
            int row = id >> 3, ch = (id & 7) << 3;   // 64 halves = 8 chunks
            cp_async16(sb + (uint32_t)(row * G_LD + ch) * 2u,
                       A + (size_t)(brow * 128 + row) * K + kt * 64 + ch);
        }
        #pragma unroll
        for (int i = 0; i < 8; i++) {
            int id = tid + i * 128;
            int row = id >> 3, ch = (id & 7) << 3;
            cp_async16(sb + (uint32_t)(G_BHALF + row * G_LD + ch) * 2u,
                       Bt + (size_t)(bcol * 128 + row) * K + kt * 64 + ch);
        }
        cp_commit();
    };

    float acc[4][8][4];
    #pragma unroll
    for (int i = 0; i < 4; i++)
        #pragma unroll
        for (int j = 0; j < 8; j++)
            #pragma unroll
            for (int e = 0; e < 4; e++) acc[i][j][e] = 0.f;

    issue_stage(0, 0);
    issue_stage(1, 1);

    // ldmatrix lane-address components (halves)
    const int lA_row = lane & 15;           // row within 16-row strip
    const int lA_col = (lane >> 4) * 8;     // k-half select
    const int lB_row = (lane & 7) + (lane >> 4) * 8;   // row within 16-n block
    const int lB_col = ((lane >> 3) & 1) * 8;          // k-half select

    uint32_t a[2][4][4], b[2][4][4];

    for (int kt = 0; kt < NT; kt++) {
        if (kt + 2 < NT) cp_wait<1>(); else cp_wait<0>();
        __syncthreads();
        if (kt + 2 < NT) issue_stage(kt + 2, (kt + 2) % 3);

        const uint32_t sAu = sbase + (uint32_t)((kt % 3) * G_STAGE_H) * 2u;
        const uint32_t sBu = sAu + G_BHALF * 2u;

        auto load_frags = [&](int ks, uint32_t af[4][4], uint32_t bf[4][4]) {
            #pragma unroll
            for (int i = 0; i < 4; i++)
                ldm_x4(af[i], sAu + (uint32_t)((wm * 64 + i * 16 + lA_row) * G_LD
                                               + ks * 16 + lA_col) * 2u);
            #pragma unroll
            for (int jp = 0; jp < 4; jp++)
                ldm_x4(bf[jp], sBu + (uint32_t)((wn * 64 + jp * 16 + lB_row) * G_LD
                                                + ks * 16 + lB_col) * 2u);
        };

        load_frags(0, a[0], b[0]);
        #pragma unroll
        for (int ks = 0; ks < 4; ks++) {
            const int cur = ks & 1;
            if (ks < 3) load_frags(ks + 1, a[cur ^ 1], b[cur ^ 1]);
            #pragma unroll
            for (int i = 0; i < 4; i++)
                #pragma unroll
                for (int jp = 0; jp < 4; jp++) {
                    mma_f16(acc[i][2 * jp],     a[cur][i], &b[cur][jp][0]);
                    mma_f16(acc[i][2 * jp + 1], a[cur][i], &b[cur][jp][2]);
                }
        }
        __syncthreads();
    }

    // epilogue
    #pragma unroll
    for (int i = 0; i < 4; i++) {
        const int gm0 = brow * 128 + wm * 64 + i * 16 + r4;
        #pragma unroll
        for (int j = 0; j < 8; j++) {
            const int gn = bcol * 128 + wn * 64 + j * 8 + c4 * 2;
            const float b0 = bias[gn], b1 = bias[gn + 1];
            const float v00 = acc[i][j][0] + b0, v01 = acc[i][j][1] + b1;
            const float v10 = acc[i][j][2] + b0, v11 = acc[i][j][3] + b1;
            if (mode == 0) {
                *(float2*)(Cf + (size_t)gm0 * N + gn)       = make_float2(v00, v01);
                *(float2*)(Cf + (size_t)(gm0 + 8) * N + gn) = make_float2(v10, v11);
            } else if (gn < 2048) {
                *(__half2*)(qkh + (size_t)gm0 * 2048 + gn)       = __floats2half2_rn(v00, v01);
                *(__half2*)(qkh + (size_t)(gm0 + 8) * 2048 + gn) = __floats2half2_rn(v10, v11);
            } else {
                const int d = gn - 2048;
                vt[(size_t)d       * MROWS + gm0]     = __float2half_rn(v00);
                vt[(size_t)(d + 1) * MROWS + gm0]     = __float2half_rn(v01);
                vt[(size_t)d       * MROWS + gm0 + 8] = __float2half_rn(v10);
                vt[(size_t)(d + 1) * MROWS + gm0 + 8] = __float2half_rn(v11);
            }
        }
    }
}

// ---------------------------------------------------------------------------
// Flash attention fp16: mma.sync m16n8k16 + ldmatrix, fp32 online softmax.
// Grid (32, NH, BB), 128 threads (4 warps), warp m16 strip, BKV=64, D=64.
// SMEM (halves, LD=72): Q @0, P @4608, K dbl @9216/@13824, Vt dbl @18432/@23040.
// Total 27648 halves = 55296 B. K tile [key][d]; V tile [d_out][key] (g_vt).
// ---------------------------------------------------------------------------
#define FH_Q 0
#define FH_P 4608
#define FH_K 9216
#define FH_V 18432
#define FLASH_SMEM_B (27648 * 2)

__global__ __launch_bounds__(128, 3)
void flash_h(const __half* __restrict__ qkh, const __half* __restrict__ vt,
             __half* __restrict__ y)
{
    extern __shared__ __half smh[];
    const uint32_t sbase = smem_u32(smh);
    const int tid  = threadIdx.x;
    const int lane = tid & 31;
    const int w    = tid >> 5;
    const int r4   = lane >> 2;
    const int c4   = lane & 3;
    const int qt   = gridDim.x - 1 - blockIdx.x;   // big tiles first
    const int h    = blockIdx.y;
    const int b    = blockIdx.z;

    const __half* qg = qkh + (size_t)(b * TT + qt * 64) * 2048 + h * 64;
    const __half* kg = qkh + (size_t)(b * TT) * 2048 + 1024 + h * 64;
    const __half* vg = vt + (size_t)(h * 64) * MROWS + b * TT;

    auto issue_q = [&]() {
        #pragma unroll
        for (int i = 0; i < 4; i++) {
            int id = tid + i * 128;
            int row = id >> 3, ch = (id & 7) << 3;
            cp_async16(sbase + (uint32_t)(FH_Q + row * 72 + ch) * 2u,
                       qg + (size_t)row * 2048 + ch);
        }
    };
    auto issue_kv = [&](int j, int buf) {
        #pragma unroll
        for (int i = 0; i < 4; i++) {
            int id = tid + i * 128;
            int row = id >> 3, ch = (id & 7) << 3;
            cp_async16(sbase + (uint32_t)(FH_K + buf * 4608 + row * 72 + ch) * 2u,
                       kg + (size_t)(j * 64 + row) * 2048 + ch);
        }
        #pragma unroll
        for (int i = 0; i < 4; i++) {
            int id = tid + i * 128;
            int row = id >> 3, ch = (id & 7) << 3;   // row = d, ch = key chunk
            cp_async16(sbase + (uint32_t)(FH_V + buf * 4608 + row * 72 + ch) * 2u,
                       vg + (size_t)row * MROWS + j * 64 + ch);
        }
    };

    issue_q();
    issue_kv(0, 0);
    cp_commit();

    // ldmatrix lane-address components (halves)
    const int lA_row = lane & 15;
    const int lA_col = (lane >> 4) * 8;
    const int lB_row = (lane & 7) + (lane >> 4) * 8;
    const int lB_col = ((lane >> 3) & 1) * 8;

    uint32_t qa[4][4];
    float o[8][4];
    #pragma unroll
    for (int j2 = 0; j2 < 8; j2++)
        #pragma unroll
        for (int e = 0; e < 4; e++) o[j2][e] = 0.f;
    float m0 = -INFINITY, m1 = -INFINITY, l0 = 0.f, l1 = 0.f;

    for (int j = 0; j <= qt; j++) {
        cp_wait<0>();
        __syncthreads();
        if (j < qt) { issue_kv(j + 1, (j + 1) & 1); cp_commit(); }

        if (j == 0) {
            #pragma unroll
            for (int ks = 0; ks < 4; ks++)
                ldm_x4(qa[ks], sbase + (uint32_t)(FH_Q + (w * 16 + lA_row) * 72
                                                  + ks * 16 + lA_col) * 2u);
        }

        const uint32_t Ku = sbase + (uint32_t)(FH_K + (j & 1) * 4608) * 2u;
        const uint32_t Vu = sbase + (uint32_t)(FH_V + (j & 1) * 4608) * 2u;
        const uint32_t Pu = sbase + (uint32_t)FH_P * 2u;

        // S = Q @ K^T  (warp: m16 x n64)
        float c[8][4];
        #pragma unroll
        for (int j2 = 0; j2 < 8; j2++)
            #pragma unroll
            for (int e = 0; e < 4; e++) c[j2][e] = 0.f;

        #pragma unroll
        for (int ks = 0; ks < 4; ks++) {
            uint32_t bk[4][4];
            #pragma unroll
            for (int jp = 0; jp < 4; jp++)
                ldm_x4(bk[jp], Ku + (uint32_t)((jp * 16 + lB_row) * 72
                                               + ks * 16 + lB_col) * 2u);
            #pragma unroll
            for (int jp = 0; jp < 4; jp++) {
                mma_f16(c[2 * jp],     qa[ks], &bk[jp][0]);
                mma_f16(c[2 * jp + 1], qa[ks], &bk[jp][2]);
            }
        }

        // scale, then causal mask on diagonal tile
        #pragma unroll
        for (int j2 = 0; j2 < 8; j2++) {
            c[j2][0] *= 0.125f; c[j2][1] *= 0.125f;
            c[j2][2] *= 0.125f; c[j2][3] *= 0.125f;
        }
        if (j == qt) {
            const int row0 = w * 16 + r4, row1 = row0 + 8;
            #pragma unroll
            for (int j2 = 0; j2 < 8; j2++) {
                const int col = j2 * 8 + 2 * c4;
                if (col     > row0) c[j2][0] = -INFINITY;
                if (col + 1 > row0) c[j2][1] = -INFINITY;
                if (col     > row1) c[j2][2] = -INFINITY;
                if (col + 1 > row1) c[j2][3] = -INFINITY;
            }
        }

        // online softmax (rows r4 / r4+8, quad-reduced)
        float mx0 = -INFINITY, mx1 = -INFINITY;
        #pragma unroll
        for (int j2 = 0; j2 < 8; j2++) {
            mx0 = fmaxf(mx0, fmaxf(c[j2][0], c[j2][1]));
            mx1 = fmaxf(mx1, fmaxf(c[j2][2], c[j2][3]));
        }
        mx0 = fmaxf(mx0, __shfl_xor_sync(0xffffffffu, mx0, 1));
        mx0 = fmaxf(mx0, __shfl_xor_sync(0xffffffffu, mx0, 2));
        mx1 = fmaxf(mx1, __shfl_xor_sync(0xffffffffu, mx1, 1));
        mx1 = fmaxf(mx1, __shfl_xor_sync(0xffffffffu, mx1, 2));

        const float mn0 = fmaxf(m0, mx0), mn1 = fmaxf(m1, mx1);
        const float al0 = __expf(m0 - mn0), al1 = __expf(m1 - mn1);
        m0 = mn0; m1 = mn1;

        float ps0 = 0.f, ps1 = 0.f;
        #pragma unroll
        for (int j2 = 0; j2 < 8; j2++) {
            c[j2][0] = __expf(c[j2][0] - mn0);
            c[j2][1] = __expf(c[j2][1] - mn0);
            c[j2][2] = __expf(c[j2][2] - mn1);
            c[j2][3] = __expf(c[j2][3] - mn1);
            ps0 += c[j2][0] + c[j2][1];
            ps1 += c[j2][2] + c[j2][3];
        }
        ps0 += __shfl_xor_sync(0xffffffffu, ps0, 1);
        ps0 += __shfl_xor_sync(0xffffffffu, ps0, 2);
        ps1 += __shfl_xor_sync(0xffffffffu, ps1, 1);
        ps1 += __shfl_xor_sync(0xffffffffu, ps1, 2);
        l0 = l0 * al0 + ps0;
        l1 = l1 * al1 + ps1;

        #pragma unroll
        for (int j2 = 0; j2 < 8; j2++) {
            o[j2][0] *= al0; o[j2][1] *= al0;
            o[j2][2] *= al1; o[j2][3] *= al1;
        }

        // write P (half) to per-warp smem strip, reload as A-frags
        #pragma unroll
        for (int j2 = 0; j2 < 8; j2++) {
            *(__half2*)(smh + FH_P + (w * 16 + r4) * 72 + j2 * 8 + 2 * c4)
                = __floats2half2_rn(c[j2][0], c[j2][1]);
            *(__half2*)(smh + FH_P + (w * 16 + r4 + 8) * 72 + j2 * 8 + 2 * c4)
                = __floats2half2_rn(c[j2][2], c[j2][3]);
        }
        __syncwarp();

        // O += P @ V
        #pragma unroll
        for (int ks = 0; ks < 4; ks++) {
            uint32_t pa[4];
            ldm_x4(pa, Pu + (uint32_t)((w * 16 + lA_row) * 72 + ks * 16 + lA_col) * 2u);
            uint32_t bv[4][4];
            #pragma unroll
            for (int jp = 0; jp < 4; jp++)
                ldm_x4(bv[jp], Vu + (uint32_t)((jp * 16 + lB_row) * 72
                                               + ks * 16 + lB_col) * 2u);
            #pragma unroll
            for (int jp = 0; jp < 4; jp++) {
                mma_f16(o[2 * jp],     pa, &bv[jp][0]);
                mma_f16(o[2 * jp + 1], pa, &bv[jp][2]);
            }
        }
        __syncwarp();
    }

    // final store (half, feeds proj GEMM)
    const float il0 = 1.f / l0, il1 = 1.f / l1;
    const int gr0 = qt * 64 + w * 16 + r4;
    #pragma unroll
    for (int j2 = 0; j2 < 8; j2++) {
        const int col = h * HD + j2 * 8 + 2 * c4;
        *(__half2*)(y + (size_t)((size_t)b * TT + gr0) * CC + col)
            = __floats2half2_rn(o[j2][0] * il0, o[j2][1] * il0);
        *(__half2*)(y + (size_t)((size_t)b * TT + gr0 + 8) * CC + col)
            = __floats2half2_rn(o[j2][2] * il1, o[j2][3] * il1);
    }
}

// ---------------------------------------------------------------------------
extern "C" void kernel_launch(void* const* d_in, const int* in_sizes, int n_in,
                              void* d_out, int out_size)
{
    const float* x      = (const float*)d_in[0];
    const float* w_attn = (const float*)d_in[1];
    const float* b_attn = (const float*)d_in[2];
    const float* w_proj = (const float*)d_in[3];
    const float* b_proj = (const float*)d_in[4];
    float* out = (float*)d_out;

    __half *qk, *vt, *xh, *waT, *wpT, *yh;
    cudaGetSymbolAddress((void**)&qk,  g_qk);
    cudaGetSymbolAddress((void**)&vt,  g_vt);
    cudaGetSymbolAddress((void**)&xh,  g_xh);
    cudaGetSymbolAddress((void**)&waT, g_waT);
    cudaGetSymbolAddress((void**)&wpT, g_wpT);
    cudaGetSymbolAddress((void**)&yh,  g_yh);

    cudaFuncSetAttribute(gemm_h, cudaFuncAttributeMaxDynamicSharedMemorySize, G_SMEM_B);
    cudaFuncSetAttribute(flash_h, cudaFuncAttributeMaxDynamicSharedMemorySize, FLASH_SMEM_B);

    // prep: x -> half, weights -> half transposed
    conv_half<<<512, 256>>>(x, xh, MROWS * CC / 4);
    transpose_half<<<dim3(3 * CC / 32, CC / 32), dim3(32, 8)>>>(w_attn, waT, CC, 3 * CC);
    transpose_half<<<dim3(CC / 32, CC / 32), dim3(32, 8)>>>(w_proj, wpT, CC, CC);

    // 1) qkv = x @ w_attn + b_attn  (fp16 mma; Q,K -> g_qk; V -> g_vt transposed)
    gemm_h<<<dim3(3 * CC / 128, MROWS / 128), 128, G_SMEM_B>>>(
        xh, waT, b_attn, nullptr, qk, vt, MROWS, 3 * CC, CC, 1);

    // 2) flash attention (fp16 mma) -> g_yh
    flash_h<<<dim3(TT / 64, NH, BB), 128, FLASH_SMEM_B>>>(qk, vt, yh);

    // 3) out = y @ w_proj + b_proj  (fp16 mma; fp32 output)
    gemm_h<<<dim3(CC / 128, MROWS / 128), 128, G_SMEM_B>>>(
        yh, wpT, b_proj, out, nullptr, nullptr, MROWS, CC, CC, 0);
}

// round 14
// speedup vs baseline: 1.0514x; 1.0411x over previous
#include <cuda_runtime.h>
#include <cuda_fp16.h>
#include <math.h>
#include <stdint.h>

// Problem dims (fixed by the reference)
#define BB 2
#define TT 2048
#define CC 1024
#define NH 16
#define HD 64
#define MROWS (BB*TT)   // 4096

// Scratch (allocation-free rule: __device__ globals)
__device__ __half g_qk[(size_t)MROWS * 2 * CC];   // Q,K packed [t][2048] half
__device__ __half g_vt[(size_t)CC * MROWS];       // V^T [h*64+d][b*TT+t] half
__device__ __half g_xh[(size_t)MROWS * CC];       // x as half [M][K]
__device__ __half g_waT[(size_t)(3*CC) * CC];     // w_attn^T [3C][C] half
__device__ __half g_wpT[(size_t)CC * CC];         // w_proj^T [C][C] half
__device__ __half g_yh[(size_t)MROWS * CC];       // attention out half [M][C]

// ---------------------------------------------------------------------------
// mma.sync m16n8k16 fp16 -> fp32 accum
__device__ __forceinline__ void mma_f16(float c[4], const uint32_t a[4], const uint32_t b[2]) {
    asm volatile(
        "mma.sync.aligned.m16n8k16.row.col.f32.f16.f16.f32 "
        "{%0,%1,%2,%3}, {%4,%5,%6,%7}, {%8,%9}, {%0,%1,%2,%3};"
        : "+f"(c[0]), "+f"(c[1]), "+f"(c[2]), "+f"(c[3])
        : "r"(a[0]), "r"(a[1]), "r"(a[2]), "r"(a[3]), "r"(b[0]), "r"(b[1]));
}

// ldmatrix x4: one instruction loads four 8x8 b16 matrices (A-frag or 2 B-frags)
__device__ __forceinline__ void ldm_x4(uint32_t r[4], uint32_t addr) {
    asm volatile("ldmatrix.sync.aligned.m8n8.x4.shared.b16 {%0,%1,%2,%3}, [%4];"
        : "=r"(r[0]), "=r"(r[1]), "=r"(r[2]), "=r"(r[3]) : "r"(addr));
}

__device__ __forceinline__ uint32_t smem_u32(const void* p) {
    uint32_t a;
    asm("{ .reg .u64 t; cvta.to.shared.u64 t, %1; cvt.u32.u64 %0, t; }" : "=r"(a) : "l"(p));
    return a;
}
__device__ __forceinline__ void cp_async16(uint32_t dst, const void* src) {
    asm volatile("cp.async.cg.shared.global [%0], [%1], 16;" :: "r"(dst), "l"(src) : "memory");
}
__device__ __forceinline__ void cp_commit() {
    asm volatile("cp.async.commit_group;" ::: "memory");
}
template <int N>
__device__ __forceinline__ void cp_wait() {
    asm volatile("cp.async.wait_group %0;" :: "n"(N) : "memory");
}
__device__ __forceinline__ uint32_t pack_h2(float x, float y) {
    __half2 h = __floats2half2_rn(x, y);
    return *(uint32_t*)&h;
}

// ---------------------------------------------------------------------------
// prep kernels: x -> half; both weights -> half transposed [N][K] (one launch)
// ---------------------------------------------------------------------------
__global__ void conv_half(const float* __restrict__ in, __half* __restrict__ out, int n4) {
    int i = blockIdx.x * blockDim.x + threadIdx.x;
    int stride = gridDim.x * blockDim.x;
    for (; i < n4; i += stride) {
        float4 v = ((const float4*)in)[i];
        ((__half2*)out)[2 * i + 0] = __floats2half2_rn(v.x, v.y);
        ((__half2*)out)[2 * i + 1] = __floats2half2_rn(v.z, v.w);
    }
}

// z=0: w_attn [1024][3072] -> waT [3072][1024]; z=1: w_proj [1024][1024] -> wpT
__global__ void transpose_both(const float* __restrict__ wa, __half* __restrict__ waT,
                               const float* __restrict__ wp, __half* __restrict__ wpT) {
    __shared__ float tile[32][33];
    const int z = blockIdx.z;
    const int NW = z ? CC : 3 * CC;
    if (blockIdx.x * 32 >= NW) return;
    const float* in = z ? wp : wa;
    __half* out = z ? wpT : waT;
    const int n0 = blockIdx.x * 32, k0 = blockIdx.y * 32;
    #pragma unroll
    for (int r = threadIdx.y; r < 32; r += 8)
        tile[r][threadIdx.x] = in[(size_t)(k0 + r) * NW + n0 + threadIdx.x];
    __syncthreads();
    #pragma unroll
    for (int r = threadIdx.y; r < 32; r += 8)
        out[(size_t)(n0 + r) * CC + k0 + threadIdx.x] = __float2half_rn(tile[threadIdx.x][r]);
}

// ---------------------------------------------------------------------------
// fp16 mma.sync GEMM v6 (unchanged from R13 — at HMMA-rate ceiling):
// CTA 128x128, BK=64, 128 threads (4 warps, 2x2), warp tile 64x64,
// register double-buffered fragments, cp.async 3-stage pipeline.
// ---------------------------------------------------------------------------
#define G_LD 72
#define G_STAGE_H 18432   // halves per stage
#define G_BHALF 9216      // B offset within stage (halves)
#define G_SMEM_B (3 * G_STAGE_H * 2)   // 110592

__global__ __launch_bounds__(128, 2)
void gemm_h(const __half* __restrict__ A, const __half* __restrict__ Bt,
            const float* __restrict__ bias, float* __restrict__ Cf,
            __half* __restrict__ qkh, __half* __restrict__ vt,
            int M, int N, int K, int mode)
{
    extern __shared__ __half smh[];
    const uint32_t sbase = smem_u32(smh);
    const int tid  = threadIdx.x;
    const int lane = tid & 31;
    const int wid  = tid >> 5;
    const int wm   = wid & 1;
    const int wn   = wid >> 1;
    const int brow = blockIdx.y, bcol = blockIdx.x;
    const int r4 = lane >> 2, c4 = lane & 3;

    const int NT = K / 64;

    auto issue_stage = [&](int kt, int s) {
        const uint32_t sb = sbase + (uint32_t)s * (G_STAGE_H * 2);
        #pragma unroll
        for (int i = 0; i < 8; i++) {
            int id = tid + i * 128;
            int row = id >> 3, ch = (id & 7) << 3;
            cp_async16(sb + (uint32_t)(row * G_LD + ch) * 2u,
                       A + (size_t)(brow * 128 + row) * K + kt * 64 + ch);
        }
        #pragma unroll
        for (int i = 0; i < 8; i++) {
            int id = tid + i * 128;
            int row = id >> 3, ch = (id & 7) << 3;
            cp_async16(sb + (uint32_t)(G_BHALF + row * G_LD + ch) * 2u,
                       Bt + (size_t)(bcol * 128 + row) * K + kt * 64 + ch);
        }
        cp_commit();
    };

    float acc[4][8][4];
    #pragma unroll
    for (int i = 0; i < 4; i++)
        #pragma unroll
        for (int j = 0; j < 8; j++)
            #pragma unroll
            for (int e = 0; e < 4; e++) acc[i][j][e] = 0.f;

    issue_stage(0, 0);
    issue_stage(1, 1);

    const int lA_row = lane & 15;
    const int lA_col = (lane >> 4) * 8;
    const int lB_row = (lane & 7) + (lane >> 4) * 8;
    const int lB_col = ((lane >> 3) & 1) * 8;

    uint32_t a[2][4][4], b[2][4][4];

    for (int kt = 0; kt < NT; kt++) {
        if (kt + 2 < NT) cp_wait<1>(); else cp_wait<0>();
        __syncthreads();
        if (kt + 2 < NT) issue_stage(kt + 2, (kt + 2) % 3);

        const uint32_t sAu = sbase + (uint32_t)((kt % 3) * G_STAGE_H) * 2u;
        const uint32_t sBu = sAu + G_BHALF * 2u;

        auto load_frags = [&](int ks, uint32_t af[4][4], uint32_t bf[4][4]) {
            #pragma unroll
            for (int i = 0; i < 4; i++)
                ldm_x4(af[i], sAu + (uint32_t)((wm * 64 + i * 16 + lA_row) * G_LD
                                               + ks * 16 + lA_col) * 2u);
            #pragma unroll
            for (int jp = 0; jp < 4; jp++)
                ldm_x4(bf[jp], sBu + (uint32_t)((wn * 64 + jp * 16 + lB_row) * G_LD
                                                + ks * 16 + lB_col) * 2u);
        };

        load_frags(0, a[0], b[0]);
        #pragma unroll
        for (int ks = 0; ks < 4; ks++) {
            const int cur = ks & 1;
            if (ks < 3) load_frags(ks + 1, a[cur ^ 1], b[cur ^ 1]);
            #pragma unroll
            for (int i = 0; i < 4; i++)
                #pragma unroll
                for (int jp = 0; jp < 4; jp++) {
                    mma_f16(acc[i][2 * jp],     a[cur][i], &b[cur][jp][0]);
                    mma_f16(acc[i][2 * jp + 1], a[cur][i], &b[cur][jp][2]);
                }
        }
        __syncthreads();
    }

    #pragma unroll
    for (int i = 0; i < 4; i++) {
        const int gm0 = brow * 128 + wm * 64 + i * 16 + r4;
        #pragma unroll
        for (int j = 0; j < 8; j++) {
            const int gn = bcol * 128 + wn * 64 + j * 8 + c4 * 2;
            const float b0 = bias[gn], b1 = bias[gn + 1];
            const float v00 = acc[i][j][0] + b0, v01 = acc[i][j][1] + b1;
            const float v10 = acc[i][j][2] + b0, v11 = acc[i][j][3] + b1;
            if (mode == 0) {
                *(float2*)(Cf + (size_t)gm0 * N + gn)       = make_float2(v00, v01);
                *(float2*)(Cf + (size_t)(gm0 + 8) * N + gn) = make_float2(v10, v11);
            } else if (gn < 2048) {
                *(__half2*)(qkh + (size_t)gm0 * 2048 + gn)       = __floats2half2_rn(v00, v01);
                *(__half2*)(qkh + (size_t)(gm0 + 8) * 2048 + gn) = __floats2half2_rn(v10, v11);
            } else {
                const int d = gn - 2048;
                vt[(size_t)d       * MROWS + gm0]     = __float2half_rn(v00);
                vt[(size_t)(d + 1) * MROWS + gm0]     = __float2half_rn(v01);
                vt[(size_t)d       * MROWS + gm0 + 8] = __float2half_rn(v10);
                vt[(size_t)(d + 1) * MROWS + gm0 + 8] = __float2half_rn(v11);
            }
        }
    }
}

// ---------------------------------------------------------------------------
// Flash attention fp16 v3: P converted C-frag -> A-frag IN REGISTERS
// (no P smem buffer, no extra syncwarp). mma.sync + ldmatrix, fp32 softmax.
// Grid (32, NH, BB), 128 threads (4 warps), warp m16 strip, BKV=64, D=64.
// SMEM (halves, LD=72): Q @0, K dbl @4608/@9216, Vt dbl @13824/@18432.
// Total 23040 halves = 46080 B.
// ---------------------------------------------------------------------------
#define FH_Q 0
#define FH_K 4608
#define FH_V 13824
#define FLASH_SMEM_B (23040 * 2)

__global__ __launch_bounds__(128, 3)
void flash_h(const __half* __restrict__ qkh, const __half* __restrict__ vt,
             __half* __restrict__ y)
{
    extern __shared__ __half smh[];
    const uint32_t sbase = smem_u32(smh);
    const int tid  = threadIdx.x;
    const int lane = tid & 31;
    const int w    = tid >> 5;
    const int r4   = lane >> 2;
    const int c4   = lane & 3;
    const int qt   = gridDim.x - 1 - blockIdx.x;   // big tiles first
    const int h    = blockIdx.y;
    const int b    = blockIdx.z;

    const __half* qg = qkh + (size_t)(b * TT + qt * 64) * 2048 + h * 64;
    const __half* kg = qkh + (size_t)(b * TT) * 2048 + 1024 + h * 64;
    const __half* vg = vt + (size_t)(h * 64) * MROWS + b * TT;

    auto issue_q = [&]() {
        #pragma unroll
        for (int i = 0; i < 4; i++) {
            int id = tid + i * 128;
            int row = id >> 3, ch = (id & 7) << 3;
            cp_async16(sbase + (uint32_t)(FH_Q + row * 72 + ch) * 2u,
                       qg + (size_t)row * 2048 + ch);
        }
    };
    auto issue_kv = [&](int j, int buf) {
        #pragma unroll
        for (int i = 0; i < 4; i++) {
            int id = tid + i * 128;
            int row = id >> 3, ch = (id & 7) << 3;
            cp_async16(sbase + (uint32_t)(FH_K + buf * 4608 + row * 72 + ch) * 2u,
                       kg + (size_t)(j * 64 + row) * 2048 + ch);
        }
        #pragma unroll
        for (int i = 0; i < 4; i++) {
            int id = tid + i * 128;
            int row = id >> 3, ch = (id & 7) << 3;   // row = d, ch = key chunk
            cp_async16(sbase + (uint32_t)(FH_V + buf * 4608 + row * 72 + ch) * 2u,
                       vg + (size_t)row * MROWS + j * 64 + ch);
        }
    };

    issue_q();
    issue_kv(0, 0);
    cp_commit();

    // ldmatrix lane-address components (halves)
    const int lA_row = lane & 15;
    const int lA_col = (lane >> 4) * 8;
    const int lB_row = (lane & 7) + (lane >> 4) * 8;
    const int lB_col = ((lane >> 3) & 1) * 8;

    uint32_t qa[4][4];
    float o[8][4];
    #pragma unroll
    for (int j2 = 0; j2 < 8; j2++)
        #pragma unroll
        for (int e = 0; e < 4; e++) o[j2][e] = 0.f;
    float m0 = -INFINITY, m1 = -INFINITY, l0 = 0.f, l1 = 0.f;

    for (int j = 0; j <= qt; j++) {
        cp_wait<0>();
        __syncthreads();
        if (j < qt) { issue_kv(j + 1, (j + 1) & 1); cp_commit(); }

        if (j == 0) {
            #pragma unroll
            for (int ks = 0; ks < 4; ks++)
                ldm_x4(qa[ks], sbase + (uint32_t)(FH_Q + (w * 16 + lA_row) * 72
                                                  + ks * 16 + lA_col) * 2u);
        }

        const uint32_t Ku = sbase + (uint32_t)(FH_K + (j & 1) * 4608) * 2u;
        const uint32_t Vu = sbase + (uint32_t)(FH_V + (j & 1) * 4608) * 2u;

        // S = Q @ K^T  (warp: m16 x n64)
        float c[8][4];
        #pragma unroll
        for (int j2 = 0; j2 < 8; j2++)
            #pragma unroll
            for (int e = 0; e < 4; e++) c[j2][e] = 0.f;

        #pragma unroll
        for (int ks = 0; ks < 4; ks++) {
            uint32_t bk[4][4];
            #pragma unroll
            for (int jp = 0; jp < 4; jp++)
                ldm_x4(bk[jp], Ku + (uint32_t)((jp * 16 + lB_row) * 72
                                               + ks * 16 + lB_col) * 2u);
            #pragma unroll
            for (int jp = 0; jp < 4; jp++) {
                mma_f16(c[2 * jp],     qa[ks], &bk[jp][0]);
                mma_f16(c[2 * jp + 1], qa[ks], &bk[jp][2]);
            }
        }

        // scale, then causal mask on diagonal tile
        #pragma unroll
        for (int j2 = 0; j2 < 8; j2++) {
            c[j2][0] *= 0.125f; c[j2][1] *= 0.125f;
            c[j2][2] *= 0.125f; c[j2][3] *= 0.125f;
        }
        if (j == qt) {
            const int row0 = w * 16 + r4, row1 = row0 + 8;
            #pragma unroll
            for (int j2 = 0; j2 < 8; j2++) {
                const int col = j2 * 8 + 2 * c4;
                if (col     > row0) c[j2][0] = -INFINITY;
                if (col + 1 > row0) c[j2][1] = -INFINITY;
                if (col     > row1) c[j2][2] = -INFINITY;
                if (col + 1 > row1) c[j2][3] = -INFINITY;
            }
        }

        // online softmax (rows r4 / r4+8, quad-reduced)
        float mx0 = -INFINITY, mx1 = -INFINITY;
        #pragma unroll
        for (int j2 = 0; j2 < 8; j2++) {
            mx0 = fmaxf(mx0, fmaxf(c[j2][0], c[j2][1]));
            mx1 = fmaxf(mx1, fmaxf(c[j2][2], c[j2][3]));
        }
        mx0 = fmaxf(mx0, __shfl_xor_sync(0xffffffffu, mx0, 1));
        mx0 = fmaxf(mx0, __shfl_xor_sync(0xffffffffu, mx0, 2));
        mx1 = fmaxf(mx1, __shfl_xor_sync(0xffffffffu, mx1, 1));
        mx1 = fmaxf(mx1, __shfl_xor_sync(0xffffffffu, mx1, 2));

        const float mn0 = fmaxf(m0, mx0), mn1 = fmaxf(m1, mx1);
        const float al0 = __expf(m0 - mn0), al1 = __expf(m1 - mn1);
        m0 = mn0; m1 = mn1;

        float ps0 = 0.f, ps1 = 0.f;
        #pragma unroll
        for (int j2 = 0; j2 < 8; j2++) {
            c[j2][0] = __expf(c[j2][0] - mn0);
            c[j2][1] = __expf(c[j2][1] - mn0);
            c[j2][2] = __expf(c[j2][2] - mn1);
            c[j2][3] = __expf(c[j2][3] - mn1);
            ps0 += c[j2][0] + c[j2][1];
            ps1 += c[j2][2] + c[j2][3];
        }
        ps0 += __shfl_xor_sync(0xffffffffu, ps0, 1);
        ps0 += __shfl_xor_sync(0xffffffffu, ps0, 2);
        ps1 += __shfl_xor_sync(0xffffffffu, ps1, 1);
        ps1 += __shfl_xor_sync(0xffffffffu, ps1, 2);
        l0 = l0 * al0 + ps0;
        l1 = l1 * al1 + ps1;

        #pragma unroll
        for (int j2 = 0; j2 < 8; j2++) {
            o[j2][0] *= al0; o[j2][1] *= al0;
            o[j2][2] *= al1; o[j2][3] *= al1;
        }

        // O += P @ V ; P A-fragments built IN REGISTERS from the C-fragments:
        // k-step ks keys [16ks,16ks+16): a0=(r,2c4..+1)=c[2ks][0,1],
        // a1=(r+8,..)=c[2ks][2,3], a2=(r,+8)=c[2ks+1][0,1], a3=c[2ks+1][2,3].
        #pragma unroll
        for (int ks = 0; ks < 4; ks++) {
            uint32_t pa[4];
            pa[0] = pack_h2(c[2 * ks][0],     c[2 * ks][1]);
            pa[1] = pack_h2(c[2 * ks][2],     c[2 * ks][3]);
            pa[2] = pack_h2(c[2 * ks + 1][0], c[2 * ks + 1][1]);
            pa[3] = pack_h2(c[2 * ks + 1][2], c[2 * ks + 1][3]);
            uint32_t bv[4][4];
            #pragma unroll
            for (int jp = 0; jp < 4; jp++)
                ldm_x4(bv[jp], Vu + (uint32_t)((jp * 16 + lB_row) * 72
                                               + ks * 16 + lB_col) * 2u);
            #pragma unroll
            for (int jp = 0; jp < 4; jp++) {
                mma_f16(o[2 * jp],     pa, &bv[jp][0]);
                mma_f16(o[2 * jp + 1], pa, &bv[jp][2]);
            }
        }
    }

    // final store (half, feeds proj GEMM)
    const float il0 = 1.f / l0, il1 = 1.f / l1;
    const int gr0 = qt * 64 + w * 16 + r4;
    #pragma unroll
    for (int j2 = 0; j2 < 8; j2++) {
        const int col = h * HD + j2 * 8 + 2 * c4;
        *(__half2*)(y + (size_t)((size_t)b * TT + gr0) * CC + col)
            = __floats2half2_rn(o[j2][0] * il0, o[j2][1] * il0);
        *(__half2*)(y + (size_t)((size_t)b * TT + gr0 + 8) * CC + col)
            = __floats2half2_rn(o[j2][2] * il1, o[j2][3] * il1);
    }
}

// ---------------------------------------------------------------------------
extern "C" void kernel_launch(void* const* d_in, const int* in_sizes, int n_in,
                              void* d_out, int out_size)
{
    const float* x      = (const float*)d_in[0];
    const float* w_attn = (const float*)d_in[1];
    const float* b_attn = (const float*)d_in[2];
    const float* w_proj = (const float*)d_in[3];
    const float* b_proj = (const float*)d_in[4];
    float* out = (float*)d_out;

    __half *qk, *vt, *xh, *waT, *wpT, *yh;
    cudaGetSymbolAddress((void**)&qk,  g_qk);
    cudaGetSymbolAddress((void**)&vt,  g_vt);
    cudaGetSymbolAddress((void**)&xh,  g_xh);
    cudaGetSymbolAddress((void**)&waT, g_waT);
    cudaGetSymbolAddress((void**)&wpT, g_wpT);
    cudaGetSymbolAddress((void**)&yh,  g_yh);

    cudaFuncSetAttribute(gemm_h, cudaFuncAttributeMaxDynamicSharedMemorySize, G_SMEM_B);
    cudaFuncSetAttribute(flash_h, cudaFuncAttributeMaxDynamicSharedMemorySize, FLASH_SMEM_B);

    // prep: x -> half; both weights -> half transposed (one launch)
    conv_half<<<512, 256>>>(x, xh, MROWS * CC / 4);
    transpose_both<<<dim3(3 * CC / 32, CC / 32, 2), dim3(32, 8)>>>(w_attn, waT, w_proj, wpT);

    // 1) qkv = x @ w_attn + b_attn  (fp16 mma; Q,K -> g_qk; V -> g_vt transposed)
    gemm_h<<<dim3(3 * CC / 128, MROWS / 128), 128, G_SMEM_B>>>(
        xh, waT, b_attn, nullptr, qk, vt, MROWS, 3 * CC, CC, 1);

    // 2) flash attention (fp16 mma) -> g_yh
    flash_h<<<dim3(TT / 64, NH, BB), 128, FLASH_SMEM_B>>>(qk, vt, yh);

    // 3) out = y @ w_proj + b_proj  (fp16 mma; fp32 output)
    gemm_h<<<dim3(CC / 128, MROWS / 128), 128, G_SMEM_B>>>(
        yh, wpT, b_proj, out, nullptr, nullptr, MROWS, CC, CC, 0);
}

// round 15
// speedup vs baseline: 1.0634x; 1.0113x over previous
#include <cuda_runtime.h>
#include <cuda_fp16.h>
#include <math.h>
#include <stdint.h>

// Problem dims (fixed by the reference)
#define BB 2
#define TT 2048
#define CC 1024
#define NH 16
#define HD 64
#define MROWS (BB*TT)   // 4096

// Q is pre-scaled into the log2 domain: S_log2 = (q*k) * 0.125 * log2(e)
#define QSCALE (0.125f * 1.44269504088896f)

// Scratch (allocation-free rule: __device__ globals)
__device__ __half g_qk[(size_t)MROWS * 2 * CC];   // Q(log2-scaled),K packed [t][2048] half
__device__ __half g_vt[(size_t)CC * MROWS];       // V^T [h*64+d][b*TT+t] half
__device__ __half g_xh[(size_t)MROWS * CC];       // x as half [M][K]
__device__ __half g_waT[(size_t)(3*CC) * CC];     // w_attn^T [3C][C] half
__device__ __half g_wpT[(size_t)CC * CC];         // w_proj^T [C][C] half
__device__ __half g_yh[(size_t)MROWS * CC];       // attention out half [M][C]

// ---------------------------------------------------------------------------
// mma.sync m16n8k16 fp16 -> fp32 accum
__device__ __forceinline__ void mma_f16(float c[4], const uint32_t a[4], const uint32_t b[2]) {
    asm volatile(
        "mma.sync.aligned.m16n8k16.row.col.f32.f16.f16.f32 "
        "{%0,%1,%2,%3}, {%4,%5,%6,%7}, {%8,%9}, {%0,%1,%2,%3};"
        : "+f"(c[0]), "+f"(c[1]), "+f"(c[2]), "+f"(c[3])
        : "r"(a[0]), "r"(a[1]), "r"(a[2]), "r"(a[3]), "r"(b[0]), "r"(b[1]));
}

// ldmatrix x4: one instruction loads four 8x8 b16 matrices (A-frag or 2 B-frags)
__device__ __forceinline__ void ldm_x4(uint32_t r[4], uint32_t addr) {
    asm volatile("ldmatrix.sync.aligned.m8n8.x4.shared.b16 {%0,%1,%2,%3}, [%4];"
        : "=r"(r[0]), "=r"(r[1]), "=r"(r[2]), "=r"(r[3]) : "r"(addr));
}

__device__ __forceinline__ uint32_t smem_u32(const void* p) {
    uint32_t a;
    asm("{ .reg .u64 t; cvta.to.shared.u64 t, %1; cvt.u32.u64 %0, t; }" : "=r"(a) : "l"(p));
    return a;
}
__device__ __forceinline__ void cp_async16(uint32_t dst, const void* src) {
    asm volatile("cp.async.cg.shared.global [%0], [%1], 16;" :: "r"(dst), "l"(src) : "memory");
}
__device__ __forceinline__ void cp_commit() {
    asm volatile("cp.async.commit_group;" ::: "memory");
}
template <int N>
__device__ __forceinline__ void cp_wait() {
    asm volatile("cp.async.wait_group %0;" :: "n"(N) : "memory");
}
__device__ __forceinline__ uint32_t pack_h2(float x, float y) {
    __half2 h = __floats2half2_rn(x, y);
    return *(uint32_t*)&h;
}
__device__ __forceinline__ float ex2f(float x) {
    float r;
    asm("ex2.approx.f32 %0, %1;" : "=f"(r) : "f"(x));
    return r;
}

// ---------------------------------------------------------------------------
// prep kernels: x -> half; both weights -> half transposed [N][K] (one launch)
// ---------------------------------------------------------------------------
__global__ void conv_half(const float* __restrict__ in, __half* __restrict__ out, int n4) {
    int i = blockIdx.x * blockDim.x + threadIdx.x;
    int stride = gridDim.x * blockDim.x;
    for (; i < n4; i += stride) {
        float4 v = ((const float4*)in)[i];
        ((__half2*)out)[2 * i + 0] = __floats2half2_rn(v.x, v.y);
        ((__half2*)out)[2 * i + 1] = __floats2half2_rn(v.z, v.w);
    }
}

// z=0: w_attn [1024][3072] -> waT [3072][1024]; z=1: w_proj [1024][1024] -> wpT
__global__ void transpose_both(const float* __restrict__ wa, __half* __restrict__ waT,
                               const float* __restrict__ wp, __half* __restrict__ wpT) {
    __shared__ float tile[32][33];
    const int z = blockIdx.z;
    const int NW = z ? CC : 3 * CC;
    if (blockIdx.x * 32 >= NW) return;
    const float* in = z ? wp : wa;
    __half* out = z ? wpT : waT;
    const int n0 = blockIdx.x * 32, k0 = blockIdx.y * 32;
    #pragma unroll
    for (int r = threadIdx.y; r < 32; r += 8)
        tile[r][threadIdx.x] = in[(size_t)(k0 + r) * NW + n0 + threadIdx.x];
    __syncthreads();
    #pragma unroll
    for (int r = threadIdx.y; r < 32; r += 8)
        out[(size_t)(n0 + r) * CC + k0 + threadIdx.x] = __float2half_rn(tile[threadIdx.x][r]);
}

// ---------------------------------------------------------------------------
// fp16 mma.sync GEMM (at HMMA-rate ceiling; structure unchanged from R13):
// CTA 128x128, BK=64, 128 threads (4 warps, 2x2), warp tile 64x64,
// register double-buffered fragments, cp.async 3-stage pipeline.
// mode 1 (QKV): Q cols (<1024) scaled by QSCALE (log2 domain) -> qkh;
//               K cols (1024..2047) -> qkh; V cols -> vt transposed.
// ---------------------------------------------------------------------------
#define G_LD 72
#define G_STAGE_H 18432   // halves per stage
#define G_BHALF 9216      // B offset within stage (halves)
#define G_SMEM_B (3 * G_STAGE_H * 2)   // 110592

__global__ __launch_bounds__(128, 2)
void gemm_h(const __half* __restrict__ A, const __half* __restrict__ Bt,
            const float* __restrict__ bias, float* __restrict__ Cf,
            __half* __restrict__ qkh, __half* __restrict__ vt,
            int M, int N, int K, int mode)
{
    extern __shared__ __half smh[];
    const uint32_t sbase = smem_u32(smh);
    const int tid  = threadIdx.x;
    const int lane = tid & 31;
    const int wid  = tid >> 5;
    const int wm   = wid & 1;
    const int wn   = wid >> 1;
    const int brow = blockIdx.y, bcol = blockIdx.x;
    const int r4 = lane >> 2, c4 = lane & 3;

    const int NT = K / 64;

    auto issue_stage = [&](int kt, int s) {
        const uint32_t sb = sbase + (uint32_t)s * (G_STAGE_H * 2);
        #pragma unroll
        for (int i = 0; i < 8; i++) {
            int id = tid + i * 128;
            int row = id >> 3, ch = (id & 7) << 3;
            cp_async16(sb + (uint32_t)(row * G_LD + ch) * 2u,
                       A + (size_t)(brow * 128 + row) * K + kt * 64 + ch);
        }
        #pragma unroll
        for (int i = 0; i < 8; i++) {
            int id = tid + i * 128;
            int row = id >> 3, ch = (id & 7) << 3;
            cp_async16(sb + (uint32_t)(G_BHALF + row * G_LD + ch) * 2u,
                       Bt + (size_t)(bcol * 128 + row) * K + kt * 64 + ch);
        }
        cp_commit();
    };

    float acc[4][8][4];
    #pragma unroll
    for (int i = 0; i < 4; i++)
        #pragma unroll
        for (int j = 0; j < 8; j++)
            #pragma unroll
            for (int e = 0; e < 4; e++) acc[i][j][e] = 0.f;

    issue_stage(0, 0);
    issue_stage(1, 1);

    const int lA_row = lane & 15;
    const int lA_col = (lane >> 4) * 8;
    const int lB_row = (lane & 7) + (lane >> 4) * 8;
    const int lB_col = ((lane >> 3) & 1) * 8;

    uint32_t a[2][4][4], b[2][4][4];

    for (int kt = 0; kt < NT; kt++) {
        if (kt + 2 < NT) cp_wait<1>(); else cp_wait<0>();
        __syncthreads();
        if (kt + 2 < NT) issue_stage(kt + 2, (kt + 2) % 3);

        const uint32_t sAu = sbase + (uint32_t)((kt % 3) * G_STAGE_H) * 2u;
        const uint32_t sBu = sAu + G_BHALF * 2u;

        auto load_frags = [&](int ks, uint32_t af[4][4], uint32_t bf[4][4]) {
            #pragma unroll
            for (int i = 0; i < 4; i++)
                ldm_x4(af[i], sAu + (uint32_t)((wm * 64 + i * 16 + lA_row) * G_LD
                                               + ks * 16 + lA_col) * 2u);
            #pragma unroll
            for (int jp = 0; jp < 4; jp++)
                ldm_x4(bf[jp], sBu + (uint32_t)((wn * 64 + jp * 16 + lB_row) * G_LD
                                                + ks * 16 + lB_col) * 2u);
        };

        load_frags(0, a[0], b[0]);
        #pragma unroll
        for (int ks = 0; ks < 4; ks++) {
            const int cur = ks & 1;
            if (ks < 3) load_frags(ks + 1, a[cur ^ 1], b[cur ^ 1]);
            #pragma unroll
            for (int i = 0; i < 4; i++)
                #pragma unroll
                for (int jp = 0; jp < 4; jp++) {
                    mma_f16(acc[i][2 * jp],     a[cur][i], &b[cur][jp][0]);
                    mma_f16(acc[i][2 * jp + 1], a[cur][i], &b[cur][jp][2]);
                }
        }
        __syncthreads();
    }

    #pragma unroll
    for (int i = 0; i < 4; i++) {
        const int gm0 = brow * 128 + wm * 64 + i * 16 + r4;
        #pragma unroll
        for (int j = 0; j < 8; j++) {
            const int gn = bcol * 128 + wn * 64 + j * 8 + c4 * 2;
            const float b0 = bias[gn], b1 = bias[gn + 1];
            const float v00 = acc[i][j][0] + b0, v01 = acc[i][j][1] + b1;
            const float v10 = acc[i][j][2] + b0, v11 = acc[i][j][3] + b1;
            if (mode == 0) {
                *(float2*)(Cf + (size_t)gm0 * N + gn)       = make_float2(v00, v01);
                *(float2*)(Cf + (size_t)(gm0 + 8) * N + gn) = make_float2(v10, v11);
            } else if (gn < 1024) {   // Q: pre-scale into log2 domain
                *(__half2*)(qkh + (size_t)gm0 * 2048 + gn)
                    = __floats2half2_rn(v00 * QSCALE, v01 * QSCALE);
                *(__half2*)(qkh + (size_t)(gm0 + 8) * 2048 + gn)
                    = __floats2half2_rn(v10 * QSCALE, v11 * QSCALE);
            } else if (gn < 2048) {   // K
                *(__half2*)(qkh + (size_t)gm0 * 2048 + gn)       = __floats2half2_rn(v00, v01);
                *(__half2*)(qkh + (size_t)(gm0 + 8) * 2048 + gn) = __floats2half2_rn(v10, v11);
            } else {                  // V transposed
                const int d = gn - 2048;
                vt[(size_t)d       * MROWS + gm0]     = __float2half_rn(v00);
                vt[(size_t)(d + 1) * MROWS + gm0]     = __float2half_rn(v01);
                vt[(size_t)d       * MROWS + gm0 + 8] = __float2half_rn(v10);
                vt[(size_t)(d + 1) * MROWS + gm0 + 8] = __float2half_rn(v11);
            }
        }
    }
}

// ---------------------------------------------------------------------------
// Flash attention fp16 v4: log2-domain softmax (ex2.approx), l via ones-MMA,
// ballot-gated O rescale, P C-frag -> A-frag in registers.
// Grid (32, NH, BB), 128 threads (4 warps), warp m16 strip, BKV=64, D=64.
// SMEM (halves, LD=72): Q @0, K dbl @4608/@9216, Vt dbl @13824/@18432.
// Total 23040 halves = 46080 B.
// ---------------------------------------------------------------------------
#define FH_Q 0
#define FH_K 4608
#define FH_V 13824
#define FLASH_SMEM_B (23040 * 2)

__global__ __launch_bounds__(128, 3)
void flash_h(const __half* __restrict__ qkh, const __half* __restrict__ vt,
             __half* __restrict__ y)
{
    extern __shared__ __half smh[];
    const uint32_t sbase = smem_u32(smh);
    const int tid  = threadIdx.x;
    const int lane = tid & 31;
    const int w    = tid >> 5;
    const int r4   = lane >> 2;
    const int c4   = lane & 3;
    const int qt   = gridDim.x - 1 - blockIdx.x;   // big tiles first
    const int h    = blockIdx.y;
    const int b    = blockIdx.z;

    const __half* qg = qkh + (size_t)(b * TT + qt * 64) * 2048 + h * 64;
    const __half* kg = qkh + (size_t)(b * TT) * 2048 + 1024 + h * 64;
    const __half* vg = vt + (size_t)(h * 64) * MROWS + b * TT;

    auto issue_q = [&]() {
        #pragma unroll
        for (int i = 0; i < 4; i++) {
            int id = tid + i * 128;
            int row = id >> 3, ch = (id & 7) << 3;
            cp_async16(sbase + (uint32_t)(FH_Q + row * 72 + ch) * 2u,
                       qg + (size_t)row * 2048 + ch);
        }
    };
    auto issue_kv = [&](int j, int buf) {
        #pragma unroll
        for (int i = 0; i < 4; i++) {
            int id = tid + i * 128;
            int row = id >> 3, ch = (id & 7) << 3;
            cp_async16(sbase + (uint32_t)(FH_K + buf * 4608 + row * 72 + ch) * 2u,
                       kg + (size_t)(j * 64 + row) * 2048 + ch);
        }
        #pragma unroll
        for (int i = 0; i < 4; i++) {
            int id = tid + i * 128;
            int row = id >> 3, ch = (id & 7) << 3;   // row = d, ch = key chunk
            cp_async16(sbase + (uint32_t)(FH_V + buf * 4608 + row * 72 + ch) * 2u,
                       vg + (size_t)row * MROWS + j * 64 + ch);
        }
    };

    issue_q();
    issue_kv(0, 0);
    cp_commit();

    // ldmatrix lane-address components (halves)
    const int lA_row = lane & 15;
    const int lA_col = (lane >> 4) * 8;
    const int lB_row = (lane & 7) + (lane >> 4) * 8;
    const int lB_col = ((lane >> 3) & 1) * 8;

    uint32_t qa[4][4];
    float o[8][4];
    #pragma unroll
    for (int j2 = 0; j2 < 8; j2++)
        #pragma unroll
        for (int e = 0; e < 4; e++) o[j2][e] = 0.f;
    float lacc[4] = {0.f, 0.f, 0.f, 0.f};   // l via ones-MMA ([0]: row r4, [2]: r4+8)
    float m0 = -INFINITY, m1 = -INFINITY;
    const uint32_t ones2[2] = {0x3C003C00u, 0x3C003C00u};  // half2(1,1) x2

    for (int j = 0; j <= qt; j++) {
        cp_wait<0>();
        __syncthreads();
        if (j < qt) { issue_kv(j + 1, (j + 1) & 1); cp_commit(); }

        if (j == 0) {
            #pragma unroll
            for (int ks = 0; ks < 4; ks++)
                ldm_x4(qa[ks], sbase + (uint32_t)(FH_Q + (w * 16 + lA_row) * 72
                                                  + ks * 16 + lA_col) * 2u);
        }

        const uint32_t Ku = sbase + (uint32_t)(FH_K + (j & 1) * 4608) * 2u;
        const uint32_t Vu = sbase + (uint32_t)(FH_V + (j & 1) * 4608) * 2u;

        // S = Q @ K^T (log2 domain; Q pre-scaled)
        float c[8][4];
        #pragma unroll
        for (int j2 = 0; j2 < 8; j2++)
            #pragma unroll
            for (int e = 0; e < 4; e++) c[j2][e] = 0.f;

        #pragma unroll
        for (int ks = 0; ks < 4; ks++) {
            uint32_t bk[4][4];
            #pragma unroll
            for (int jp = 0; jp < 4; jp++)
                ldm_x4(bk[jp], Ku + (uint32_t)((jp * 16 + lB_row) * 72
                                               + ks * 16 + lB_col) * 2u);
            #pragma unroll
            for (int jp = 0; jp < 4; jp++) {
                mma_f16(c[2 * jp],     qa[ks], &bk[jp][0]);
                mma_f16(c[2 * jp + 1], qa[ks], &bk[jp][2]);
            }
        }

        // causal mask on diagonal tile
        if (j == qt) {
            const int row0 = w * 16 + r4, row1 = row0 + 8;
            #pragma unroll
            for (int j2 = 0; j2 < 8; j2++) {
                const int col = j2 * 8 + 2 * c4;
                if (col     > row0) c[j2][0] = -INFINITY;
                if (col + 1 > row0) c[j2][1] = -INFINITY;
                if (col     > row1) c[j2][2] = -INFINITY;
                if (col + 1 > row1) c[j2][3] = -INFINITY;
            }
        }

        // online softmax (log2 domain; rows r4 / r4+8, quad-reduced max)
        float mx0 = -INFINITY, mx1 = -INFINITY;
        #pragma unroll
        for (int j2 = 0; j2 < 8; j2++) {
            mx0 = fmaxf(mx0, fmaxf(c[j2][0], c[j2][1]));
            mx1 = fmaxf(mx1, fmaxf(c[j2][2], c[j2][3]));
        }
        mx0 = fmaxf(mx0, __shfl_xor_sync(0xffffffffu, mx0, 1));
        mx0 = fmaxf(mx0, __shfl_xor_sync(0xffffffffu, mx0, 2));
        mx1 = fmaxf(mx1, __shfl_xor_sync(0xffffffffu, mx1, 1));
        mx1 = fmaxf(mx1, __shfl_xor_sync(0xffffffffu, mx1, 2));

        const float mn0 = fmaxf(m0, mx0), mn1 = fmaxf(m1, mx1);
        const bool need = (mn0 != m0) || (mn1 != m1);
        const uint32_t bal = __ballot_sync(0xffffffffu, need);
        if (bal) {
            const float al0 = ex2f(m0 - mn0), al1 = ex2f(m1 - mn1);
            #pragma unroll
            for (int j2 = 0; j2 < 8; j2++) {
                o[j2][0] *= al0; o[j2][1] *= al0;
                o[j2][2] *= al1; o[j2][3] *= al1;
            }
            lacc[0] *= al0; lacc[2] *= al1;
            m0 = mn0; m1 = mn1;
        }

        // O += P @ V and l += P @ 1 ; P = ex2(c - m) packed straight into
        // A-fragments (C-frag layout == A-frag layout for the PV product).
        #pragma unroll
        for (int ks = 0; ks < 4; ks++) {
            uint32_t pa[4];
            pa[0] = pack_h2(ex2f(c[2 * ks][0] - m0),     ex2f(c[2 * ks][1] - m0));
            pa[1] = pack_h2(ex2f(c[2 * ks][2] - m1),     ex2f(c[2 * ks][3] - m1));
            pa[2] = pack_h2(ex2f(c[2 * ks + 1][0] - m0), ex2f(c[2 * ks + 1][1] - m0));
            pa[3] = pack_h2(ex2f(c[2 * ks + 1][2] - m1), ex2f(c[2 * ks + 1][3] - m1));
            uint32_t bv[4][4];
            #pragma unroll
            for (int jp = 0; jp < 4; jp++)
                ldm_x4(bv[jp], Vu + (uint32_t)((jp * 16 + lB_row) * 72
                                               + ks * 16 + lB_col) * 2u);
            #pragma unroll
            for (int jp = 0; jp < 4; jp++) {
                mma_f16(o[2 * jp],     pa, &bv[jp][0]);
                mma_f16(o[2 * jp + 1], pa, &bv[jp][2]);
            }
            mma_f16(lacc, pa, ones2);   // row sums -> l
        }
    }

    // final store (half, feeds proj GEMM)
    const float il0 = 1.f / lacc[0], il1 = 1.f / lacc[2];
    const int gr0 = qt * 64 + w * 16 + r4;
    #pragma unroll
    for (int j2 = 0; j2 < 8; j2++) {
        const int col = h * HD + j2 * 8 + 2 * c4;
        *(__half2*)(y + (size_t)((size_t)b * TT + gr0) * CC + col)
            = __floats2half2_rn(o[j2][0] * il0, o[j2][1] * il0);
        *(__half2*)(y + (size_t)((size_t)b * TT + gr0 + 8) * CC + col)
            = __floats2half2_rn(o[j2][2] * il1, o[j2][3] * il1);
    }
}

// ---------------------------------------------------------------------------
extern "C" void kernel_launch(void* const* d_in, const int* in_sizes, int n_in,
                              void* d_out, int out_size)
{
    const float* x      = (const float*)d_in[0];
    const float* w_attn = (const float*)d_in[1];
    const float* b_attn = (const float*)d_in[2];
    const float* w_proj = (const float*)d_in[3];
    const float* b_proj = (const float*)d_in[4];
    float* out = (float*)d_out;

    __half *qk, *vt, *xh, *waT, *wpT, *yh;
    cudaGetSymbolAddress((void**)&qk,  g_qk);
    cudaGetSymbolAddress((void**)&vt,  g_vt);
    cudaGetSymbolAddress((void**)&xh,  g_xh);
    cudaGetSymbolAddress((void**)&waT, g_waT);
    cudaGetSymbolAddress((void**)&wpT, g_wpT);
    cudaGetSymbolAddress((void**)&yh,  g_yh);

    cudaFuncSetAttribute(gemm_h, cudaFuncAttributeMaxDynamicSharedMemorySize, G_SMEM_B);
    cudaFuncSetAttribute(flash_h, cudaFuncAttributeMaxDynamicSharedMemorySize, FLASH_SMEM_B);

    // prep: x -> half; both weights -> half transposed (one launch)
    conv_half<<<512, 256>>>(x, xh, MROWS * CC / 4);
    transpose_both<<<dim3(3 * CC / 32, CC / 32, 2), dim3(32, 8)>>>(w_attn, waT, w_proj, wpT);

    // 1) qkv = x @ w_attn + b_attn  (fp16 mma; Q log2-scaled, K -> g_qk; V -> g_vt^T)
    gemm_h<<<dim3(3 * CC / 128, MROWS / 128), 128, G_SMEM_B>>>(
        xh, waT, b_attn, nullptr, qk, vt, MROWS, 3 * CC, CC, 1);

    // 2) flash attention (fp16 mma, log2-domain softmax) -> g_yh
    flash_h<<<dim3(TT / 64, NH, BB), 128, FLASH_SMEM_B>>>(qk, vt, yh);

    // 3) out = y @ w_proj + b_proj  (fp16 mma; fp32 output)
    gemm_h<<<dim3(CC / 128, MROWS / 128), 128, G_SMEM_B>>>(
        yh, wpT, b_proj, out, nullptr, nullptr, MROWS, CC, CC, 0);
}